// round 16
// baseline (speedup 1.0000x reference)
#include <cuda_runtime.h>
#include <cuda_fp16.h>
#include <cstdint>

#define NB 1024
#define NSEQ 144
#define NH 4
#define NJOBS (NB * NH)
#define GRID_P 444              // 3 CTAs x 148 SMs, persistent
// qk scale * log2(e): softmax computed in base-2 (exp2), shift-free
#define QK_SCALE_L2E (0.17677669529663687f * 1.4426950408889634f)
#define LOG2E 1.4426950408889634f

#define SKW 20   // K/Q row stride (words): conflict-free frag reads
#define SVW 76   // V^T row stride (words): conflict-free B-frag reads
#define SOW 40   // out-transpose row stride (floats): conflict-free STS.64/LDS.128

// per-buffer smem layout (32-bit words); two buffers ping-pong.
#define OFF_Q 0                       // [144][20]
#define OFF_K (OFF_Q + NSEQ * SKW)    // [144][20]
#define OFF_V (OFF_K + NSEQ * SKW)    // [32][76]
#define BUF_WORDS (OFF_V + 32 * SVW)  // 8192 words = 32 KB per buffer

// Mask (x log2e) fp16 fragment pairs for LDG.128:
// [h][warp][chunk(9)][lane] -> uint4 { nt0 lo/hi, nt1 lo/hi }
__device__ uint4 g_mfrag4[NH * 9 * 9 * 32];   // 162 KB, L2-resident

__device__ __forceinline__ unsigned pack_h2(float lo, float hi) {
    __half2 hv = __floats2half2_rn(lo, hi);
    return *reinterpret_cast<unsigned*>(&hv);
}

__device__ __forceinline__ float ex2(float x) {
    float r;
    asm("ex2.approx.f32 %0, %1;" : "=f"(r) : "f"(x));
    return r;
}

__device__ __forceinline__ void mma_f16(float c[4],
                                        unsigned a0, unsigned a1, unsigned a2, unsigned a3,
                                        unsigned b0, unsigned b1) {
    asm volatile(
        "mma.sync.aligned.m16n8k16.row.col.f32.f16.f16.f32 "
        "{%0,%1,%2,%3}, {%4,%5,%6,%7}, {%8,%9}, {%0,%1,%2,%3};"
        : "+f"(c[0]), "+f"(c[1]), "+f"(c[2]), "+f"(c[3])
        : "r"(a0), "r"(a1), "r"(a2), "r"(a3), "r"(b0), "r"(b1));
}

// Reorder mask (1,4,144,144) into fp16 fragment order (x log2e).
__global__ void mask_transpose_kernel(const float* __restrict__ mask) {
    int hw   = blockIdx.x;          // h*9 + w
    int h    = hw / 9;
    int w    = hw % 9;
    int ntp  = threadIdx.x >> 5;    // chunk 0..8
    int lane = threadIdx.x & 31;
    int g    = lane >> 2;
    int t4   = lane & 3;
    int row  = w * 16 + g;
    uint4 r;
    {
        int col = (2 * ntp) * 8 + 2 * t4;
        const float* m0 = mask + ((size_t)h * NSEQ + row) * NSEQ + col;
        float2 a = *(const float2*)(m0);
        float2 b = *(const float2*)(m0 + 8 * NSEQ);
        r.x = pack_h2(a.x * LOG2E, a.y * LOG2E);
        r.y = pack_h2(b.x * LOG2E, b.y * LOG2E);
    }
    {
        int col = (2 * ntp + 1) * 8 + 2 * t4;
        const float* m0 = mask + ((size_t)h * NSEQ + row) * NSEQ + col;
        float2 a = *(const float2*)(m0);
        float2 b = *(const float2*)(m0 + 8 * NSEQ);
        r.z = pack_h2(a.x * LOG2E, a.y * LOG2E);
        r.w = pack_h2(b.x * LOG2E, b.y * LOG2E);
    }
    g_mfrag4[(hw * 9 + ntp) * 32 + lane] = r;
}

// Stage one quarter (it=0..3) of a job's Q/K/V into a buffer.
__device__ __forceinline__ void stage_rows(unsigned* buf, const float* base,
                                           int tid, int it) {
    unsigned* sQ = buf + OFF_Q;
    unsigned* sK = buf + OFF_K;
    unsigned* sV = buf + OFF_V;
    int idx = tid + it * 288;
    int row = idx >> 3;          // seq index
    int d4  = (idx & 7) * 4;     // head-dim base
    const float* p = base + (size_t)row * 384 + d4;
    float4 q4 = *(const float4*)(p);
    float4 k4 = *(const float4*)(p + 128);
    float4 v4 = *(const float4*)(p + 256);

    unsigned q01 = pack_h2(q4.x * QK_SCALE_L2E, q4.y * QK_SCALE_L2E);
    unsigned q23 = pack_h2(q4.z * QK_SCALE_L2E, q4.w * QK_SCALE_L2E);
    *(uint2*)(sQ + row * SKW + (d4 >> 1)) = make_uint2(q01, q23);

    unsigned k01 = pack_h2(k4.x, k4.y);
    unsigned k23 = pack_h2(k4.z, k4.w);
    *(uint2*)(sK + row * SKW + (d4 >> 1)) = make_uint2(k01, k23);

    unsigned v01 = pack_h2(v4.x, v4.y);
    unsigned v23 = pack_h2(v4.z, v4.w);
    // partner lane (^8) holds key^1 at same d4
    unsigned pv01 = __shfl_xor_sync(0xffffffffu, v01, 8);
    unsigned pv23 = __shfl_xor_sync(0xffffffffu, v23, 8);
    int kw = row >> 1;
    if (!(idx & 8)) {  // even key: I am the lo half of each pair
        sV[(d4    ) * SVW + kw] = __byte_perm(v01, pv01, 0x5410);
        sV[(d4 + 1) * SVW + kw] = __byte_perm(v01, pv01, 0x7632);
    } else {           // odd key: partner (even key) is the lo half
        sV[(d4 + 2) * SVW + kw] = __byte_perm(pv23, v23, 0x5410);
        sV[(d4 + 3) * SVW + kw] = __byte_perm(pv23, v23, 0x7632);
    }
}

// Persistent kernel: 444 CTAs, 3/SM. CTA c handles jobs j = c, c+444, ...
// (h = c & 3 constant per CTA). Double-buffered smem: while computing job i
// from `cur`, job i+1 is staged into `nxt` inside the chunk loop, hiding the
// DRAM phase under compute and eliminating wave transitions.
// Shift-free base-2 softmax, fp16 mma / f32 accum, scalar LDS frag loads.
__global__ __launch_bounds__(288, 3)
void attn144_kernel(const float* __restrict__ qkv,
                    float* __restrict__ out) {
    extern __shared__ unsigned smem[];   // 2 x BUF_WORDS

    const int tid  = threadIdx.x;
    const int warp = tid >> 5;
    const int lane = tid & 31;
    const int g    = lane >> 2;
    const int t4   = lane & 3;
    const int cta  = blockIdx.x;
    const int h    = cta & 3;            // constant across this CTA's jobs

    const uint4* mf4 = g_mfrag4 + ((h * 9 + warp) * 9) * 32 + lane;

    // ---- Prologue: stage first job into buffer 0 ----
    int j = cta;
    {
        const float* base0 = qkv + (size_t)((j >> 2) * NSEQ) * 384 + h * 32;
#pragma unroll
        for (int it = 0; it < 4; it++) stage_rows(smem, base0, tid, it);
    }
    __syncthreads();

    int parity = 0;
    for (;;) {
        unsigned* cur = smem + (parity ? BUF_WORDS : 0);
        unsigned* nxt = smem + (parity ? 0 : BUF_WORDS);
        const int  jn = j + GRID_P;
        const bool hn = jn < NJOBS;
        const float* nbase = qkv + (size_t)((jn >> 2) * NSEQ) * 384 + h * 32;

        const unsigned* sQ = cur + OFF_Q;
        const unsigned* sK = cur + OFF_K;
        const unsigned* sV = cur + OFF_V;
        const int row0 = warp * 16 + g;

        // ---- Q A-fragments (conflict-free scalar LDS) ----
        unsigned a[2][4];
#pragma unroll
        for (int kt = 0; kt < 2; kt++) {
            const unsigned* q0 = sQ + row0 * SKW + kt * 8;
            const unsigned* q1 = sQ + (row0 + 8) * SKW + kt * 8;
            a[kt][0] = q0[t4];
            a[kt][1] = q1[t4];
            a[kt][2] = q0[t4 + 4];
            a[kt][3] = q1[t4 + 4];
        }

        float l0 = 0.f, l1 = 0.f;
        float o[4][4];
#pragma unroll
        for (int nt2 = 0; nt2 < 4; nt2++) {
            o[nt2][0] = 0.f; o[nt2][1] = 0.f; o[nt2][2] = 0.f; o[nt2][3] = 0.f;
        }

        auto do_chunk = [&](int ch) {
            float c[2][4];
            {
                uint4 mh = mf4[ch * 32];
                float2 f0 = __half22float2(*reinterpret_cast<__half2*>(&mh.x));
                float2 f1 = __half22float2(*reinterpret_cast<__half2*>(&mh.y));
                float2 f2 = __half22float2(*reinterpret_cast<__half2*>(&mh.z));
                float2 f3 = __half22float2(*reinterpret_cast<__half2*>(&mh.w));
                c[0][0] = f0.x; c[0][1] = f0.y; c[0][2] = f1.x; c[0][3] = f1.y;
                c[1][0] = f2.x; c[1][1] = f2.y; c[1][2] = f3.x; c[1][3] = f3.y;
            }
#pragma unroll
            for (int kt = 0; kt < 2; kt++) {
#pragma unroll
                for (int jj = 0; jj < 2; jj++) {
                    const unsigned* kr = sK + (ch * 16 + jj * 8 + g) * SKW + kt * 8;
                    mma_f16(c[jj], a[kt][0], a[kt][1], a[kt][2], a[kt][3],
                            kr[t4], kr[t4 + 4]);
                }
            }
#pragma unroll
            for (int jj = 0; jj < 2; jj++) {
                c[jj][0] = ex2(c[jj][0]);
                c[jj][1] = ex2(c[jj][1]);
                c[jj][2] = ex2(c[jj][2]);
                c[jj][3] = ex2(c[jj][3]);
            }
            l0 += (c[0][0] + c[0][1]) + (c[1][0] + c[1][1]);
            l1 += (c[0][2] + c[0][3]) + (c[1][2] + c[1][3]);

            unsigned pa0 = pack_h2(c[0][0], c[0][1]);
            unsigned pa1 = pack_h2(c[0][2], c[0][3]);
            unsigned pa2 = pack_h2(c[1][0], c[1][1]);
            unsigned pa3 = pack_h2(c[1][2], c[1][3]);
#pragma unroll
            for (int nt2 = 0; nt2 < 4; nt2++) {
                const unsigned* vr = sV + (nt2 * 8 + g) * SVW + ch * 8;
                mma_f16(o[nt2], pa0, pa1, pa2, pa3, vr[t4], vr[t4 + 4]);
            }
        };

        // ---- chunk loop with next-job staging interleaved ----
#pragma unroll
        for (int ch = 0; ch < 3; ch++) do_chunk(ch);
        if (hn) { stage_rows(nxt, nbase, tid, 0); stage_rows(nxt, nbase, tid, 1); }
#pragma unroll
        for (int ch = 3; ch < 6; ch++) do_chunk(ch);
        if (hn) { stage_rows(nxt, nbase, tid, 2); stage_rows(nxt, nbase, tid, 3); }
#pragma unroll
        for (int ch = 6; ch < 9; ch++) do_chunk(ch);

        // ---- Final row-sum reduce + normalize ----
        l0 += __shfl_xor_sync(0xffffffffu, l0, 1);
        l0 += __shfl_xor_sync(0xffffffffu, l0, 2);
        l1 += __shfl_xor_sync(0xffffffffu, l1, 1);
        l1 += __shfl_xor_sync(0xffffffffu, l1, 2);
        const float inv0 = 1.f / l0;
        const float inv1 = 1.f / l1;

        // all warps done reading cur (and done staging nxt)
        __syncthreads();

        // ---- epilogue: sO aliases cur's dead Q/K region ----
        float* sO = (float*)cur;
        float* so = sO + warp * 16 * SOW;
#pragma unroll
        for (int nt2 = 0; nt2 < 4; nt2++) {
            int col = nt2 * 8 + 2 * t4;
            *(float2*)(so + g * SOW + col) =
                make_float2(o[nt2][0] * inv0, o[nt2][1] * inv0);
            *(float2*)(so + (g + 8) * SOW + col) =
                make_float2(o[nt2][2] * inv1, o[nt2][3] * inv1);
        }
        __syncwarp();

        const int b    = j >> 2;
        const int rsub = lane >> 3;          // 0..3
        const int cw   = (lane & 7) * 4;     // 0,4,...,28
        float* ob = out + ((size_t)b * NSEQ + warp * 16 + rsub) * 128 + h * 32 + cw;
#pragma unroll
        for (int it = 0; it < 4; it++) {
            int r = it * 4 + rsub;
            float4 val = *(float4*)(so + r * SOW + cw);
            *(float4*)(ob + (size_t)it * 4 * 128) = val;
        }

        // protect sO (in cur) from next iteration's staging into cur
        __syncthreads();

        if (!hn) break;
        j = jn;
        parity ^= 1;
    }
}

extern "C" void kernel_launch(void* const* d_in, const int* in_sizes, int n_in,
                              void* d_out, int out_size) {
    const float* qkv  = (const float*)d_in[0];
    const float* mask = (const float*)d_in[1];
    float* out = (float*)d_out;

    mask_transpose_kernel<<<NH * 9, 288>>>(mask);

    const int smem_bytes = 2 * BUF_WORDS * 4;   // 65,536 B
    cudaFuncSetAttribute(attn144_kernel,
                         cudaFuncAttributeMaxDynamicSharedMemorySize, smem_bytes);

    attn144_kernel<<<GRID_P, 288, smem_bytes>>>(qkv, out);
}

// round 17
// speedup vs baseline: 1.2046x; 1.2046x over previous
#include <cuda_runtime.h>
#include <cuda_fp16.h>
#include <cstdint>

#define NB 1024
#define NSEQ 144
#define NH 4
// qk scale * log2(e): softmax computed in base-2 (exp2), shift-free
#define QK_SCALE_L2E (0.17677669529663687f * 1.4426950408889634f)
#define LOG2E 1.4426950408889634f

#define SKW 20   // K/Q row stride (words): conflict-free frag reads
#define SVW 76   // V^T row stride (words): conflict-free B-frag reads
#define SOW 40   // out-transpose row stride (floats): conflict-free STS.64/LDS.128

// smem layout (32-bit words). sO (5760 words) aliases sQ+sK (5760 words).
#define OFF_Q 0                       // [144][20]
#define OFF_K (OFF_Q + NSEQ * SKW)    // [144][20]
#define OFF_V (OFF_K + NSEQ * SKW)    // [32][76]
#define SMEM_WORDS (OFF_V + 32 * SVW) // 8192 words = 32768 B exactly

// Mask (x log2e) fp16 fragment pairs for LDG.128:
// [h][warp][chunk(9)][lane] -> uint4 { nt0 lo/hi, nt1 lo/hi }
__device__ uint4 g_mfrag4[NH * 9 * 9 * 32];   // 162 KB, L2-resident

__device__ __forceinline__ unsigned pack_h2(float lo, float hi) {
    __half2 hv = __floats2half2_rn(lo, hi);
    return *reinterpret_cast<unsigned*>(&hv);
}

__device__ __forceinline__ float ex2(float x) {
    float r;
    asm("ex2.approx.f32 %0, %1;" : "=f"(r) : "f"(x));
    return r;
}

__device__ __forceinline__ void mma_f16(float c[4],
                                        unsigned a0, unsigned a1, unsigned a2, unsigned a3,
                                        unsigned b0, unsigned b1) {
    asm volatile(
        "mma.sync.aligned.m16n8k16.row.col.f32.f16.f16.f32 "
        "{%0,%1,%2,%3}, {%4,%5,%6,%7}, {%8,%9}, {%0,%1,%2,%3};"
        : "+f"(c[0]), "+f"(c[1]), "+f"(c[2]), "+f"(c[3])
        : "r"(a0), "r"(a1), "r"(a2), "r"(a3), "r"(b0), "r"(b1));
}

// Reorder mask (1,4,144,144) into fp16 fragment order (x log2e).
// One warp per (h, w, chunk): 324 blocks x 32 threads -> latency spread wide.
__global__ void mask_transpose_kernel(const float* __restrict__ mask) {
    int bid  = blockIdx.x;          // (h*9 + w)*9 + ntp
    int ntp  = bid % 9;
    int hw   = bid / 9;             // h*9 + w
    int h    = hw / 9;
    int w    = hw % 9;
    int lane = threadIdx.x;
    int g    = lane >> 2;
    int t4   = lane & 3;
    int row  = w * 16 + g;
    uint4 r;
    {
        int col = (2 * ntp) * 8 + 2 * t4;
        const float* m0 = mask + ((size_t)h * NSEQ + row) * NSEQ + col;
        float2 a = *(const float2*)(m0);
        float2 b = *(const float2*)(m0 + 8 * NSEQ);
        r.x = pack_h2(a.x * LOG2E, a.y * LOG2E);
        r.y = pack_h2(b.x * LOG2E, b.y * LOG2E);
    }
    {
        int col = (2 * ntp + 1) * 8 + 2 * t4;
        const float* m0 = mask + ((size_t)h * NSEQ + row) * NSEQ + col;
        float2 a = *(const float2*)(m0);
        float2 b = *(const float2*)(m0 + 8 * NSEQ);
        r.z = pack_h2(a.x * LOG2E, a.y * LOG2E);
        r.w = pack_h2(b.x * LOG2E, b.y * LOG2E);
    }
    g_mfrag4[(hw * 9 + ntp) * 32 + lane] = r;
}

// One CTA per (b,h), 4 CTAs/SM, 9 warps, warp w owns query rows [16w, 16w+16).
// Shift-free base-2 softmax (logits bounded, so exp2 applied directly -- no
// max, no rescale). 9 chunks of 16 key cols keep the S accumulator at 8 regs.
// fp16 mma, f32 accum, scalar LDS fragment loads (measured faster than LDSM).
__global__ __launch_bounds__(288, 4)
void attn144_kernel(const float* __restrict__ qkv,
                    float* __restrict__ out) {
    extern __shared__ unsigned smem[];
    unsigned* sQ = smem + OFF_Q;
    unsigned* sK = smem + OFF_K;
    unsigned* sV = smem + OFF_V;
    float*    sO = (float*)smem;      // aliases sQ+sK (dead at epilogue)

    const int h    = blockIdx.x;
    const int b    = blockIdx.y;
    const int tid  = threadIdx.x;
    const int warp = tid >> 5;
    const int lane = tid & 31;
    const int g    = lane >> 2;
    const int t4   = lane & 3;

    // qkv[b, n, j, h, d] at ((b*144+n)*384 + j*128 + h*32 + d)
    const float* base = qkv + (size_t)(b * NSEQ) * 384 + h * 32;

    // ---- Stage Q (scaled by qk_scale*log2e), K, V^T (f16x2) ----
    {
        const int row_b = tid >> 3;         // base seq index (advances by 36/iter)
        const int d4    = (tid & 7) * 4;    // head-dim base
        const int evenk = !(tid & 8);
        const float* p0 = base + (size_t)row_b * 384 + d4;
#pragma unroll
        for (int it = 0; it < 4; it++) {
            int row = row_b + it * 36;
            const float* p = p0 + (size_t)it * 36 * 384;
            float4 q4 = *(const float4*)(p);
            float4 k4 = *(const float4*)(p + 128);
            float4 v4 = *(const float4*)(p + 256);

            unsigned q01 = pack_h2(q4.x * QK_SCALE_L2E, q4.y * QK_SCALE_L2E);
            unsigned q23 = pack_h2(q4.z * QK_SCALE_L2E, q4.w * QK_SCALE_L2E);
            *(uint2*)(sQ + row * SKW + (d4 >> 1)) = make_uint2(q01, q23);

            unsigned k01 = pack_h2(k4.x, k4.y);
            unsigned k23 = pack_h2(k4.z, k4.w);
            *(uint2*)(sK + row * SKW + (d4 >> 1)) = make_uint2(k01, k23);

            unsigned v01 = pack_h2(v4.x, v4.y);
            unsigned v23 = pack_h2(v4.z, v4.w);
            // partner lane (^8) holds key^1 at same d4
            unsigned pv01 = __shfl_xor_sync(0xffffffffu, v01, 8);
            unsigned pv23 = __shfl_xor_sync(0xffffffffu, v23, 8);
            int kw = row >> 1;
            if (evenk) {  // even key: I am the lo half of each pair
                sV[(d4    ) * SVW + kw] = __byte_perm(v01, pv01, 0x5410);
                sV[(d4 + 1) * SVW + kw] = __byte_perm(v01, pv01, 0x7632);
            } else {      // odd key: partner (even key) is the lo half
                sV[(d4 + 2) * SVW + kw] = __byte_perm(pv23, v23, 0x5410);
                sV[(d4 + 3) * SVW + kw] = __byte_perm(pv23, v23, 0x7632);
            }
        }
    }

    const uint4* mf4 = g_mfrag4 + ((h * 9 + warp) * 9) * 32 + lane;
    const int row0 = warp * 16 + g;
    __syncthreads();

    // ---- Q A-fragments from smem (conflict-free), reused by all chunks ----
    unsigned a[2][4];
#pragma unroll
    for (int kt = 0; kt < 2; kt++) {
        const unsigned* q0 = sQ + row0 * SKW + kt * 8;
        const unsigned* q1 = sQ + (row0 + 8) * SKW + kt * 8;
        a[kt][0] = q0[t4];
        a[kt][1] = q1[t4];
        a[kt][2] = q0[t4 + 4];
        a[kt][3] = q1[t4 + 4];
    }

    // ---- Accumulators: per-lane partial row sums + O ----
    float l0 = 0.f, l1 = 0.f;
    float o[4][4];
#pragma unroll
    for (int nt2 = 0; nt2 < 4; nt2++) {
        o[nt2][0] = 0.f; o[nt2][1] = 0.f; o[nt2][2] = 0.f; o[nt2][3] = 0.f;
    }

#pragma unroll
    for (int ch = 0; ch < 9; ch++) {
        // S chunk = mask + Q K^T over 16 key cols (2 n-tiles)
        float c[2][4];
        {
            uint4 mh = mf4[ch * 32];
            float2 f0 = __half22float2(*reinterpret_cast<__half2*>(&mh.x));
            float2 f1 = __half22float2(*reinterpret_cast<__half2*>(&mh.y));
            float2 f2 = __half22float2(*reinterpret_cast<__half2*>(&mh.z));
            float2 f3 = __half22float2(*reinterpret_cast<__half2*>(&mh.w));
            c[0][0] = f0.x; c[0][1] = f0.y; c[0][2] = f1.x; c[0][3] = f1.y;
            c[1][0] = f2.x; c[1][1] = f2.y; c[1][2] = f3.x; c[1][3] = f3.y;
        }
#pragma unroll
        for (int kt = 0; kt < 2; kt++) {
#pragma unroll
            for (int j = 0; j < 2; j++) {
                const unsigned* kr = sK + (ch * 16 + j * 8 + g) * SKW + kt * 8;
                mma_f16(c[j], a[kt][0], a[kt][1], a[kt][2], a[kt][3],
                        kr[t4], kr[t4 + 4]);
            }
        }

        // shift-free exp2 + partial sums (no max, no rescale)
#pragma unroll
        for (int j = 0; j < 2; j++) {
            c[j][0] = ex2(c[j][0]);
            c[j][1] = ex2(c[j][1]);
            c[j][2] = ex2(c[j][2]);
            c[j][3] = ex2(c[j][3]);
        }
        l0 += (c[0][0] + c[0][1]) + (c[1][0] + c[1][1]);
        l1 += (c[0][2] + c[0][3]) + (c[1][2] + c[1][3]);

        // O += P_chunk * V_chunk  (one k16 step; C-frag -> fp16 A-frag pack)
        unsigned pa0 = pack_h2(c[0][0], c[0][1]);
        unsigned pa1 = pack_h2(c[0][2], c[0][3]);
        unsigned pa2 = pack_h2(c[1][0], c[1][1]);
        unsigned pa3 = pack_h2(c[1][2], c[1][3]);
#pragma unroll
        for (int nt2 = 0; nt2 < 4; nt2++) {
            const unsigned* vr = sV + (nt2 * 8 + g) * SVW + ch * 8;
            mma_f16(o[nt2], pa0, pa1, pa2, pa3, vr[t4], vr[t4 + 4]);
        }
    }

    // ---- Final row-sum reduce + normalize ----
    l0 += __shfl_xor_sync(0xffffffffu, l0, 1);
    l0 += __shfl_xor_sync(0xffffffffu, l0, 2);
    l1 += __shfl_xor_sync(0xffffffffu, l1, 1);
    l1 += __shfl_xor_sync(0xffffffffu, l1, 2);
    const float inv0 = 1.f / l0;
    const float inv1 = 1.f / l1;

    // sO aliases sQ/sK: every warp must be done reading them first
    __syncthreads();

    // ---- Normalize -> per-warp smem transpose -> line-minimal coalesced store ----
    float* so = sO + warp * 16 * SOW;
#pragma unroll
    for (int nt2 = 0; nt2 < 4; nt2++) {
        int col = nt2 * 8 + 2 * t4;
        *(float2*)(so + g * SOW + col)       = make_float2(o[nt2][0] * inv0, o[nt2][1] * inv0);
        *(float2*)(so + (g + 8) * SOW + col) = make_float2(o[nt2][2] * inv1, o[nt2][3] * inv1);
    }
    __syncwarp();

    // out[b, n, h*32 + d]; warp covers 4 full rows (4 x 128B lines) per STG.128
    // evict-first stores: output is write-once, keep it out of the L2 stream.
    const int rsub = lane >> 3;          // 0..3
    const int cw   = (lane & 7) * 4;     // 0,4,...,28
    float* ob = out + ((size_t)b * NSEQ + warp * 16 + rsub) * 128 + h * 32 + cw;
#pragma unroll
    for (int it = 0; it < 4; it++) {
        int r = it * 4 + rsub;
        float4 val = *(float4*)(so + r * SOW + cw);
        __stcs((float4*)(ob + (size_t)it * 4 * 128), val);
    }
}

extern "C" void kernel_launch(void* const* d_in, const int* in_sizes, int n_in,
                              void* d_out, int out_size) {
    const float* qkv  = (const float*)d_in[0];
    const float* mask = (const float*)d_in[1];
    float* out = (float*)d_out;

    mask_transpose_kernel<<<NH * 9 * 9, 32>>>(mask);

    const int smem_bytes = SMEM_WORDS * 4;   // 32,768 B
    cudaFuncSetAttribute(attn144_kernel,
                         cudaFuncAttributeMaxDynamicSharedMemorySize, smem_bytes);

    dim3 grid(NH, NB);
    attn144_kernel<<<grid, 288, smem_bytes>>>(qkv, out);
}